// round 14
// baseline (speedup 1.0000x reference)
#include <cuda_runtime.h>

// Subtraction2: out[n,c,p,y*112+x] = in1[n,c,y,x] - in2_padded[n,c,y+di-3,x+dj-3]
// p = di*7+dj, 7x7 kernel, stride 1, dilation 1, pad 3. H=W=112, N=8, C=32.
// Output: 8*32*49*12544 fp32 = 629 MB -> pure HBM-write-bound kernel.
// R3 (11th resubmit; broker timeouts): two-phase dj window (8 live window regs
// instead of 12) so 8 blocks/SM fits WITHOUT spills (R2's forced 32-reg cap
// spilled, adding ~17MB local traffic). 3584/(148*8)=3.03 waves -> no tail.

#define H 112
#define W 112
#define HW (H * W)          // 12544
#define KK 49
#define TY 8                // output rows per block
#define TPB 224             // 28 x-quads * 8 rows
#define SROW 120            // smem row: cols -4..115 (16B-aligned windows)

__global__ __launch_bounds__(TPB, 8)
void sub2_kernel(const float* __restrict__ in1,
                 const float* __restrict__ in2,
                 float* __restrict__ out) {
    __shared__ float s[TY + 6][SROW];

    const int tile  = blockIdx.x;            // 0..13  (y tile)
    const int plane = blockIdx.y;            // 0..255 (n*c)
    const int y0    = tile * TY;
    const int tid   = threadIdx.x;

    const int tx = tid % 28;                 // x-quad index
    const int ty = tid / 28;                 // row within tile
    const int x  = tx * 4;
    const int y  = y0 + ty;

    // center load issued early, overlaps with smem fill
    const float4 c = *reinterpret_cast<const float4*>(
        in1 + (size_t)plane * HW + y * W + x);

    // ---- fill input2 tile (rows y0-3 .. y0+TY+2, cols -4..115, zero halo) ----
    const float* p2 = in2 + (size_t)plane * HW;
    #pragma unroll
    for (int i = tid; i < (TY + 6) * SROW; i += TPB) {
        const int r  = i / SROW;
        const int ci = i - r * SROW;
        const int gr = y0 - 3 + r;           // global row
        const int gc = ci - 4;               // global col
        float v = 0.0f;
        if ((unsigned)gr < (unsigned)H && (unsigned)gc < (unsigned)W)
            v = p2[gr * W + gc];
        s[r][ci] = v;
    }
    __syncthreads();

    float* optr = out + (size_t)plane * KK * HW + y * W + x;

    #pragma unroll
    for (int di = 0; di < 7; di++) {
        // Window of global cols x-4..x+7 lives at s[ty+di][x .. x+11]
        // (smem col of global col g is g+4). Needed window index for output
        // element e at shift dj is dj+1+e.
        // Phase A (dj=0..3): indices 1..7  -> regs w0,w1 (8 floats)
        // Phase B (dj=4..6): indices 5..10 -> regs w1,w2 (8 floats)
        const float4 w0 = *reinterpret_cast<const float4*>(&s[ty + di][x]);
        const float4 w1 = *reinterpret_cast<const float4*>(&s[ty + di][x + 4]);
        {
            float wa[8];
            wa[0] = w0.x; wa[1] = w0.y; wa[2] = w0.z; wa[3] = w0.w;
            wa[4] = w1.x; wa[5] = w1.y; wa[6] = w1.z; wa[7] = w1.w;
            #pragma unroll
            for (int dj = 0; dj < 4; dj++) {
                float4 o;
                o.x = c.x - wa[dj + 1];
                o.y = c.y - wa[dj + 2];
                o.z = c.z - wa[dj + 3];
                o.w = c.w - wa[dj + 4];
                __stcs(reinterpret_cast<float4*>(optr), o);
                optr += HW;                  // next p-plane
            }
        }
        const float4 w2 = *reinterpret_cast<const float4*>(&s[ty + di][x + 8]);
        {
            float wb[8];
            wb[0] = w1.x; wb[1] = w1.y; wb[2] = w1.z; wb[3] = w1.w;
            wb[4] = w2.x; wb[5] = w2.y; wb[6] = w2.z; wb[7] = w2.w;
            #pragma unroll
            for (int dj = 4; dj < 7; dj++) {
                float4 o;
                o.x = c.x - wb[dj - 3];
                o.y = c.y - wb[dj - 2];
                o.z = c.z - wb[dj - 1];
                o.w = c.w - wb[dj];
                __stcs(reinterpret_cast<float4*>(optr), o);
                optr += HW;                  // next p-plane
            }
        }
    }
}

extern "C" void kernel_launch(void* const* d_in, const int* in_sizes, int n_in,
                              void* d_out, int out_size) {
    const float* in1 = (const float*)d_in[0];
    const float* in2 = (const float*)d_in[1];
    float* out = (float*)d_out;

    dim3 grid(H / TY, 8 * 32);   // 14 y-tiles x 256 planes
    sub2_kernel<<<grid, TPB>>>(in1, in2, out);
}